// round 15
// baseline (speedup 1.0000x reference)
#include <cuda_runtime.h>
#include <cuda_fp16.h>
#include <cstdint>
#include <math.h>

// Problem constants
#define TSTEPS 128
#define BSZ    64
#define FSZ    1024
#define HSZ    1024
#define N4H    4096   // 4*H

// Persistent step-GEMM (fp16): 4 k-groups x (2 k-sub x 2 n-half) warps, warp tile 32x32
// Single-shot B: each group loads its full 64x256 fp16 h-slice (32 KB) once per step.
#define NCTA   128
#define MT     32
#define A_SMEM_BYTES  65536             // 32 rows x 1024 fp16 (2048B/row, swizzled, resident)
#define BG_BYTES      32768             // per-group B: 64 rows x 512B (single buffer)
#define DSMEM_BYTES   (A_SMEM_BYTES + 4 * BG_BYTES + 1024)   // 197632

// Precompute GEMM (fp16): CTA tile 128x64, warp 32x32, KT=128, 2 stages
#define PC_STAGE_BYTES 49152            // A 32 KB (128x256B) + B 16 KB (64x256B)
#define PC_DSMEM (2 * PC_STAGE_BYTES + 1024)

// ---------------- device scratch ----------------
__device__ float  g_Z[(size_t)TSTEPS * BSZ * N4H];    // [T][B][4H] x@Wx + b (fp32)
__device__ __half g_Wrh[(size_t)NCTA * MT * HSZ];     // [blk][m][k] fp16 recurrent weights
__device__ __half g_Wxth[(size_t)N4H * FSZ];          // [n][k] fp16 input weights (transposed)
__device__ __half g_Xh[(size_t)BSZ * TSTEPS * FSZ];   // fp16 copy of x
__device__ __half g_h[2][BSZ * HSZ];                  // ping-pong hidden state (fp16)
__device__ int    g_cnt[TSTEPS + 1][4];               // h(t) quarter q ready when ==32

// ---------------- helpers ----------------
__device__ __forceinline__ uint32_t smem_u32(const void* p) {
    uint32_t a;
    asm("{ .reg .u64 t; cvta.to.shared.u64 t, %1; cvt.u32.u64 %0, t; }" : "=r"(a) : "l"(p));
    return a;
}
#define CP16(dst, src) \
    asm volatile("cp.async.cg.shared.global [%0], [%1], 16;" :: "r"(dst), "l"(src) : "memory")
#define CP_COMMIT() asm volatile("cp.async.commit_group;" ::: "memory")
#define CP_WAIT1()  asm volatile("cp.async.wait_group 1;" ::: "memory")
#define CP_WAIT0()  asm volatile("cp.async.wait_group 0;" ::: "memory")
#define BARG(id)    asm volatile("bar.sync %0, 128;" :: "r"(id) : "memory")

#define LDSM_X4(r0, r1, r2, r3, addr) \
    asm volatile("ldmatrix.sync.aligned.m8n8.x4.shared.b16 {%0,%1,%2,%3}, [%4];" \
                 : "=r"(r0), "=r"(r1), "=r"(r2), "=r"(r3) : "r"(addr))

#define MMA_F16(c, a0, a1, a2, a3, b0, b1) \
    asm volatile("mma.sync.aligned.m16n8k16.row.col.f32.f16.f16.f32 " \
                 "{%0,%1,%2,%3}, {%4,%5,%6,%7}, {%8,%9}, {%0,%1,%2,%3};" \
                 : "+f"((c)[0]), "+f"((c)[1]), "+f"((c)[2]), "+f"((c)[3]) \
                 : "r"(a0), "r"(a1), "r"(a2), "r"(a3), "r"(b0), "r"(b1))

// ---------------- init: zero h[0], reset counters ----------------
__global__ void init_state_kernel() {
    int i = blockIdx.x * blockDim.x + threadIdx.x;
    if (i < BSZ * HSZ) { g_h[0][i] = __float2half(0.0f); }
    if (i < (TSTEPS + 1) * 4) { ((int*)g_cnt)[i] = (i < 4) ? 32 : 0; }
}

// ---------------- prep: x -> fp16 ----------------
__global__ void prep_x_kernel(const float* __restrict__ X) {
    int idx = (blockIdx.x * blockDim.x + threadIdx.x) * 4;
    float4 v = *(const float4*)(X + idx);
    __half2 h0 = __floats2half2_rn(v.x, v.y);
    __half2 h1 = __floats2half2_rn(v.z, v.w);
    *(uint2*)&g_Xh[idx] = make_uint2(*(uint32_t*)&h0, *(uint32_t*)&h1);
}

// ---------------- prep: recurrent weights -> [blk][m=g*8+j][k] fp16 ----------------
__global__ void prep_w_kernel(const float* __restrict__ W) {
    __shared__ float sm[32][9];
    int bx  = blockIdx.x;
    int kt  = bx & 31;
    int g   = (bx >> 5) & 3;
    int blk = bx >> 7;
    int tid = threadIdx.x;

    int jx = tid & 7;
    int ky = tid >> 3;
    sm[ky][jx] = W[(size_t)(FSZ + kt * 32 + ky) * N4H + g * HSZ + blk * 8 + jx];
    __syncthreads();

    int k2 = tid & 31;
    int j2 = tid >> 5;
    g_Wrh[((size_t)blk * MT + g * 8 + j2) * HSZ + kt * 32 + k2] = __float2half_rn(sm[k2][j2]);
}

// ---------------- prep: transpose W[0:F][4H] -> g_Wxth[n][k] fp16 ----------------
__global__ void prep_wxt_kernel(const float* __restrict__ W) {
    __shared__ float sm[32][33];
    int k0 = blockIdx.x * 32;
    int n0 = blockIdx.y * 32;
    int tx = threadIdx.x & 31;
    int ty = threadIdx.x >> 5;
#pragma unroll
    for (int r = 0; r < 4; r++) {
        int row = ty + r * 8;
        sm[row][tx] = W[(size_t)(k0 + row) * N4H + n0 + tx];
    }
    __syncthreads();
#pragma unroll
    for (int r = 0; r < 4; r++) {
        int row = ty + r * 8;
        g_Wxth[(size_t)(n0 + row) * FSZ + k0 + tx] = __float2half_rn(sm[tx][row]);
    }
}

// ---------------- precompute Z = X @ Wx + b (fp16 mma, 128x64 tile, KT=128) ----------------
__global__ __launch_bounds__(256, 2)
void precompute_mma_kernel(const float* __restrict__ bias, float* __restrict__ Z) {
    extern __shared__ char dsm_raw[];
    const uint32_t raw_base = smem_u32(dsm_raw);
    const uint32_t base     = (raw_base + 1023) & ~1023u;

    const int tid  = threadIdx.x;
    const int wid  = tid >> 5;
    const int lane = tid & 31;
    const int wm   = wid >> 1;
    const int wn   = wid & 1;
    const int n0   = blockIdx.x * 64;
    const int m0   = blockIdx.y * 128;

    const int grp = lane >> 3;
    const int r_l = lane & 7;
    const int a_row0 = wm * 32 + ((grp & 1) << 3) + r_l;
    const int a_row1 = a_row0 + 16;
    const int a_cko  = grp >> 1;
    const int b_row0 = wn * 32 + ((grp >> 1) << 3) + r_l;
    const int b_row1 = b_row0 + 16;
    const int b_cko  = grp & 1;

    float c[2][4][4];
#pragma unroll
    for (int mf = 0; mf < 2; mf++)
#pragma unroll
        for (int j = 0; j < 4; j++)
#pragma unroll
            for (int q = 0; q < 4; q++) c[mf][j][q] = 0.0f;

    auto load_tile = [&](int kt, int s) {
        const uint32_t aB = base + s * PC_STAGE_BYTES;
        const uint32_t bB = aB + 32768;
        const int k0 = kt * 128;
#pragma unroll
        for (int i = 0; i < 8; i++) {
            int id = tid + i * 256;
            int row = id >> 4;
            int u   = id & 15;
            CP16(aB + row * 256 + (((uint32_t)u ^ (row & 7)) << 4),
                 g_Xh + (size_t)(m0 + row) * FSZ + k0 + u * 8);
        }
#pragma unroll
        for (int i = 0; i < 4; i++) {
            int id = tid + i * 256;
            int row = id >> 4;
            int u   = id & 15;
            CP16(bB + row * 256 + (((uint32_t)u ^ (row & 7)) << 4),
                 g_Wxth + (size_t)(n0 + row) * FSZ + k0 + u * 8);
        }
    };

    load_tile(0, 0);
    CP_COMMIT();

    for (int kt = 0; kt < FSZ / 128; kt++) {
        if (kt + 1 < FSZ / 128) {
            load_tile(kt + 1, (kt + 1) & 1);
            CP_COMMIT();
            CP_WAIT1();
        } else {
            CP_WAIT0();
        }
        __syncthreads();

        const uint32_t aB = base + (kt & 1) * PC_STAGE_BYTES;
        const uint32_t bB = aB + 32768;
#pragma unroll
        for (int s = 0; s < 8; s++) {
            uint32_t ua = (uint32_t)(s * 2 + a_cko);
            uint32_t a00, a01, a02, a03, a10, a11, a12, a13;
            LDSM_X4(a00, a01, a02, a03,
                    aB + a_row0 * 256 + ((ua ^ (a_row0 & 7)) << 4));
            LDSM_X4(a10, a11, a12, a13,
                    aB + a_row1 * 256 + ((ua ^ (a_row1 & 7)) << 4));

            uint32_t ub = (uint32_t)(s * 2 + b_cko);
            uint32_t b00, b01, b10, b11, b20, b21, b30, b31;
            LDSM_X4(b00, b01, b10, b11,
                    bB + b_row0 * 256 + ((ub ^ (b_row0 & 7)) << 4));
            LDSM_X4(b20, b21, b30, b31,
                    bB + b_row1 * 256 + ((ub ^ (b_row1 & 7)) << 4));

            MMA_F16(c[0][0], a00, a01, a02, a03, b00, b01);
            MMA_F16(c[0][1], a00, a01, a02, a03, b10, b11);
            MMA_F16(c[0][2], a00, a01, a02, a03, b20, b21);
            MMA_F16(c[0][3], a00, a01, a02, a03, b30, b31);
            MMA_F16(c[1][0], a10, a11, a12, a13, b00, b01);
            MMA_F16(c[1][1], a10, a11, a12, a13, b10, b11);
            MMA_F16(c[1][2], a10, a11, a12, a13, b20, b21);
            MMA_F16(c[1][3], a10, a11, a12, a13, b30, b31);
        }
        __syncthreads();
    }

    const int gr = lane >> 2;
    const int qc = lane & 3;
#pragma unroll
    for (int mf = 0; mf < 2; mf++) {
#pragma unroll
        for (int j = 0; j < 4; j++) {
            int n = n0 + wn * 32 + j * 8 + 2 * qc;
            float2 bia = *(const float2*)(bias + n);
            int m1 = m0 + wm * 32 + mf * 16 + gr;
            int m2 = m1 + 8;
            float2 v1 = { c[mf][j][0] + bia.x, c[mf][j][1] + bia.y };
            float2 v2 = { c[mf][j][2] + bia.x, c[mf][j][3] + bia.y };
            *(float2*)(Z + ((size_t)(m1 & 127) * BSZ + (m1 >> 7)) * N4H + n) = v1;
            *(float2*)(Z + ((size_t)(m2 & 127) * BSZ + (m2 >> 7)) * N4H + n) = v2;
        }
    }
}

// ---------------- persistent LSTM kernel (fp16, single-shot B load per step) ----------------
// grid=128, block=512. Group g (wid>>2): k in [g*256,(g+1)*256).
// wk = (wid>>1)&1 k-half; wn = wid&1 batch half; warp tile 32(m)x32(n)xk128.
// B region per group: 64 rows x 512B (32 units of 16B per row), per-128B-chunk XOR swizzle.
__global__ __launch_bounds__(512, 1)
void lstm_persist_kernel(float* __restrict__ d_out) {
    extern __shared__ char dsm_raw[];
    const uint32_t raw_base = smem_u32(dsm_raw);
    const uint32_t base     = (raw_base + 1023) & ~1023u;
    const uint32_t aS       = base;
    float* SfAll = (float*)(dsm_raw + (base - raw_base) + A_SMEM_BYTES); // partials overlay B

    const int tid  = threadIdx.x;
    const int wid  = tid >> 5;
    const int lane = tid & 31;
    const int blk  = blockIdx.x;
    const int g    = wid >> 2;            // k-group 0..3
    const int wk   = (wid >> 1) & 1;      // k-half
    const int wn   = wid & 1;             // batch half
    const int tig  = tid & 127;
    const uint32_t bGroup = base + A_SMEM_BYTES + g * BG_BYTES;

    // ---- load resident A panel (32 rows x 1024 fp16, 2048B/row, swizzled) ----
    {
        const __half* wsrc = g_Wrh + (size_t)blk * MT * HSZ;
#pragma unroll
        for (int i = 0; i < 8; i++) {
            int uix = tid + i * 512;
            int row = uix >> 7;
            int u   = uix & 127;
            CP16(aS + row * 2048 + (((uint32_t)u ^ (row & 7)) << 4),
                 wsrc + (size_t)row * HSZ + u * 8);
        }
        CP_COMMIT();
        CP_WAIT0();
    }
    __syncthreads();

    // lane-dependent ldmatrix address components
    const int grp = lane >> 3;
    const int r_l = lane & 7;
    const int a_row0 = ((grp & 1) << 3) + r_l;
    const int a_row1 = a_row0 + 16;
    const int a_cko  = grp >> 1;
    const int b_row0 = wn * 32 + ((grp >> 1) << 3) + r_l;
    const int b_row1 = b_row0 + 16;
    const int b_cko  = grp & 1;
    const uint32_t aAddr0 = aS + a_row0 * 2048;
    const uint32_t aAddr1 = aS + a_row1 * 2048;
    const int a_sw0 = a_row0 & 7;
    const int a_sw1 = a_row1 & 7;
    const uint32_t bRow0 = bGroup + b_row0 * 512;
    const uint32_t bRow1 = bGroup + b_row1 * 512;
    const int b_sw0 = b_row0 & 7;
    const int b_sw1 = b_row1 & 7;

    // epilogue indices
    const int e_j = tid & 7;
    const int e_b = tid >> 3;
    const int e_hcol = blk * 8 + e_j;
    const int my_quarter = blk >> 5;

    float cst = 0.0f;                     // cell state (register)

    for (int t = 0; t < TSTEPS; t++) {
        const __half* __restrict__ hi = g_h[t & 1];
        __half* __restrict__ ho = g_h[(t + 1) & 1];

        float c[2][4][4];
#pragma unroll
        for (int mh = 0; mh < 2; mh++)
#pragma unroll
            for (int j = 0; j < 4; j++)
#pragma unroll
                for (int q = 0; q < 4; q++) c[mh][j][q] = 0.0f;

        // Z loads (independent of h(t); issue before the wait)
        const float* zp = g_Z + (size_t)t * BSZ * N4H + (size_t)e_b * N4H + blk * 8 + e_j;
        float z0 = __ldg(zp);
        float z1 = __ldg(zp + HSZ);
        float z2 = __ldg(zp + 2 * HSZ);
        float z3 = __ldg(zp + 3 * HSZ);

        // ---- dataflow wait: single poller per group, then group barrier ----
        if (tig == 0) {
            int v;
            const int* p = &g_cnt[t][g];
            do {
                asm volatile("ld.global.acquire.gpu.b32 %0, [%1];" : "=r"(v) : "l"(p) : "memory");
            } while (v < 32);
        }
        BARG(g + 1);

        // ---- single-shot fill: 64 rows x 32 units (32 KB), 16 CP16/thread ----
        {
            const __half* src = hi + g * 256;
#pragma unroll
            for (int i = 0; i < 16; i++) {
                int id  = tig + i * 128;      // 0..2047
                int row = id >> 5;
                int u   = id & 31;
                uint32_t su = (uint32_t)((u & 24) | ((u & 7) ^ (row & 7)));
                CP16(bGroup + row * 512 + (su << 4),
                     src + (size_t)row * HSZ + u * 8);
            }
            CP_COMMIT();
            CP_WAIT0();
        }
        BARG(g + 1);

        // ---- all 8 k16 MMA steps, no intermediate syncs ----
#pragma unroll
        for (int s = 0; s < 8; s++) {
            uint32_t ua = (uint32_t)(g * 32 + wk * 16 + s * 2 + a_cko);
            uint32_t a00, a01, a02, a03, a10, a11, a12, a13;
            LDSM_X4(a00, a01, a02, a03, aAddr0 + ((ua ^ a_sw0) << 4));
            LDSM_X4(a10, a11, a12, a13, aAddr1 + ((ua ^ a_sw1) << 4));

            uint32_t u = (uint32_t)(wk * 16 + s * 2 + b_cko);
            uint32_t su0 = (u & 24) | ((u & 7) ^ b_sw0);
            uint32_t su1 = (u & 24) | ((u & 7) ^ b_sw1);
            uint32_t b00, b01, b10, b11, b20, b21, b30, b31;
            LDSM_X4(b00, b01, b10, b11, bRow0 + (su0 << 4));
            LDSM_X4(b20, b21, b30, b31, bRow1 + (su1 << 4));

            MMA_F16(c[0][0], a00, a01, a02, a03, b00, b01);
            MMA_F16(c[0][1], a00, a01, a02, a03, b10, b11);
            MMA_F16(c[0][2], a00, a01, a02, a03, b20, b21);
            MMA_F16(c[0][3], a00, a01, a02, a03, b30, b31);
            MMA_F16(c[1][0], a10, a11, a12, a13, b00, b01);
            MMA_F16(c[1][1], a10, a11, a12, a13, b10, b11);
            MMA_F16(c[1][2], a10, a11, a12, a13, b20, b21);
            MMA_F16(c[1][3], a10, a11, a12, a13, b30, b31);
        }

        // ---- stash partials: region (g, wk), S[m*65+n], wn disjoint n ----
        {
            float* S = SfAll + g * (BG_BYTES / 4) + wk * 2080;   // 2080 = 32*65
            const int gr = lane >> 2;
            const int qc = lane & 3;
            BARG(g + 1);   // group warps done with LDSM before overwriting B region
#pragma unroll
            for (int mh = 0; mh < 2; mh++) {
#pragma unroll
                for (int j = 0; j < 4; j++) {
                    int m = mh * 16 + gr;
                    int n = wn * 32 + j * 8 + 2 * qc;
                    S[m * 65 + n]           = c[mh][j][0];
                    S[m * 65 + n + 1]       = c[mh][j][1];
                    S[(m + 8) * 65 + n]     = c[mh][j][2];
                    S[(m + 8) * 65 + n + 1] = c[mh][j][3];
                }
            }
        }
        __syncthreads();

        // ---- gate epilogue: 512 cells, 1 per thread; sum 8 partial regions + Z ----
        float z[4] = { z0, z1, z2, z3 };
#pragma unroll
        for (int gate = 0; gate < 4; gate++) {
            float s = z[gate];
            int off = (gate * 8 + e_j) * 65 + e_b;
#pragma unroll
            for (int g2 = 0; g2 < 4; g2++) {
                s += SfAll[g2 * (BG_BYTES / 4) + off];
                s += SfAll[g2 * (BG_BYTES / 4) + 2080 + off];
            }
            z[gate] = s;
        }
        float si = 1.0f / (1.0f + __expf(-z[0]));
        float sf = 1.0f / (1.0f + __expf(-(z[2] + 1.0f)));   // forget bias = 1.0
        float so = 1.0f / (1.0f + __expf(-z[3]));
        float tj = tanhf(z[1]);

        cst = cst * sf + si * tj;
        float h_new = tanhf(cst) * so;

        ho[(size_t)e_b * HSZ + e_hcol] = __float2half_rn(h_new);

        // ---- publish h(t+1) slice; d_out store overlaps next step's wait ----
        __threadfence();
        __syncthreads();
        if (tid == 0 && t + 1 < TSTEPS) {
            asm volatile("red.release.gpu.global.add.u32 [%0], %1;"
                         :: "l"(&g_cnt[t + 1][my_quarter]), "r"(1u) : "memory");
        }
        d_out[((size_t)e_b * TSTEPS + t) * HSZ + e_hcol] = h_new;
    }
}

// ---------------- launcher ----------------
extern "C" void kernel_launch(void* const* d_in, const int* in_sizes, int n_in,
                              void* d_out, int out_size) {
    const float* x = (const float*)d_in[0];   // [B, T, F]
    const float* W = (const float*)d_in[1];   // [F+H, 4H]
    const float* b = (const float*)d_in[2];   // [4H]
    float* out = (float*)d_out;               // [B, T, H]

    static bool attr_done = false;
    if (!attr_done) {
        cudaFuncSetAttribute(lstm_persist_kernel, cudaFuncAttributeMaxDynamicSharedMemorySize,
                             DSMEM_BYTES);
        cudaFuncSetAttribute(precompute_mma_kernel, cudaFuncAttributeMaxDynamicSharedMemorySize,
                             PC_DSMEM);
        attr_done = true;
    }

    float* zbuf;
    cudaGetSymbolAddress((void**)&zbuf, g_Z);

    init_state_kernel<<<(BSZ * HSZ + 255) / 256, 256>>>();
    prep_x_kernel<<<(BSZ * TSTEPS * FSZ) / (256 * 4), 256>>>(x);
    prep_w_kernel<<<NCTA * 4 * 32, 256>>>(W);
    {
        dim3 g(FSZ / 32, N4H / 32);
        prep_wxt_kernel<<<g, 256>>>(W);
    }
    {
        dim3 g(N4H / 64, (BSZ * TSTEPS) / 128);   // (64, 64)
        precompute_mma_kernel<<<g, 256, PC_DSMEM>>>(b, zbuf);
    }
    lstm_persist_kernel<<<NCTA, 512, DSMEM_BYTES>>>(out);
}

// round 16
// speedup vs baseline: 1.0277x; 1.0277x over previous
#include <cuda_runtime.h>
#include <cuda_fp16.h>
#include <cstdint>
#include <math.h>

// Problem constants
#define TSTEPS 128
#define BSZ    64
#define FSZ    1024
#define HSZ    1024
#define N4H    4096   // 4*H

// Persistent step-GEMM (fp16): 4 k-groups x (2 k-sub x 2 n-half) warps, warp tile 32x32
// B: 2 tiles of KT=128 (16 KB each), 2-stage pipeline.
#define NCTA   128
#define MT     32
#define A_SMEM_BYTES  65536             // 32 rows x 1024 fp16 (2048B/row, swizzled, resident)
#define BG_BYTES      32768             // per-group B: 2 stages x 16 KB (64 rows x 256B)
#define DSMEM_BYTES   (A_SMEM_BYTES + 4 * BG_BYTES + 1024)   // 197632

// Precompute GEMM (fp16): CTA tile 128x64, warp 32x32, KT=128, 2 stages
#define PC_STAGE_BYTES 49152            // A 32 KB (128x256B) + B 16 KB (64x256B)
#define PC_DSMEM (2 * PC_STAGE_BYTES + 1024)

// ---------------- device scratch ----------------
__device__ float  g_Z[(size_t)TSTEPS * BSZ * N4H];    // [T][B][4H] x@Wx + b (fp32)
__device__ __half g_Wrh[(size_t)NCTA * MT * HSZ];     // [blk][m][k] fp16 recurrent weights
__device__ __half g_Wxth[(size_t)N4H * FSZ];          // [n][k] fp16 input weights (transposed)
__device__ __half g_Xh[(size_t)BSZ * TSTEPS * FSZ];   // fp16 copy of x
__device__ __half g_h[2][BSZ * HSZ];                  // ping-pong hidden state (fp16)
__device__ int    g_cnt[TSTEPS + 1][4];               // h(t) quarter q ready when ==32

// ---------------- helpers ----------------
__device__ __forceinline__ uint32_t smem_u32(const void* p) {
    uint32_t a;
    asm("{ .reg .u64 t; cvta.to.shared.u64 t, %1; cvt.u32.u64 %0, t; }" : "=r"(a) : "l"(p));
    return a;
}
#define CP16(dst, src) \
    asm volatile("cp.async.cg.shared.global [%0], [%1], 16;" :: "r"(dst), "l"(src) : "memory")
#define CP_COMMIT() asm volatile("cp.async.commit_group;" ::: "memory")
#define CP_WAIT1()  asm volatile("cp.async.wait_group 1;" ::: "memory")
#define CP_WAIT0()  asm volatile("cp.async.wait_group 0;" ::: "memory")
#define BARG(id)    asm volatile("bar.sync %0, 128;" :: "r"(id) : "memory")

#define LDSM_X4(r0, r1, r2, r3, addr) \
    asm volatile("ldmatrix.sync.aligned.m8n8.x4.shared.b16 {%0,%1,%2,%3}, [%4];" \
                 : "=r"(r0), "=r"(r1), "=r"(r2), "=r"(r3) : "r"(addr))

#define MMA_F16(c, a0, a1, a2, a3, b0, b1) \
    asm volatile("mma.sync.aligned.m16n8k16.row.col.f32.f16.f16.f32 " \
                 "{%0,%1,%2,%3}, {%4,%5,%6,%7}, {%8,%9}, {%0,%1,%2,%3};" \
                 : "+f"((c)[0]), "+f"((c)[1]), "+f"((c)[2]), "+f"((c)[3]) \
                 : "r"(a0), "r"(a1), "r"(a2), "r"(a3), "r"(b0), "r"(b1))

// ---------------- init: zero h[0], reset counters ----------------
__global__ void init_state_kernel() {
    int i = blockIdx.x * blockDim.x + threadIdx.x;
    if (i < BSZ * HSZ) { g_h[0][i] = __float2half(0.0f); }
    if (i < (TSTEPS + 1) * 4) { ((int*)g_cnt)[i] = (i < 4) ? 32 : 0; }
}

// ---------------- prep: x -> fp16 ----------------
__global__ void prep_x_kernel(const float* __restrict__ X) {
    int idx = (blockIdx.x * blockDim.x + threadIdx.x) * 4;
    float4 v = *(const float4*)(X + idx);
    __half2 h0 = __floats2half2_rn(v.x, v.y);
    __half2 h1 = __floats2half2_rn(v.z, v.w);
    *(uint2*)&g_Xh[idx] = make_uint2(*(uint32_t*)&h0, *(uint32_t*)&h1);
}

// ---------------- prep: recurrent weights -> [blk][m=g*8+j][k] fp16 ----------------
__global__ void prep_w_kernel(const float* __restrict__ W) {
    __shared__ float sm[32][9];
    int bx  = blockIdx.x;
    int kt  = bx & 31;
    int g   = (bx >> 5) & 3;
    int blk = bx >> 7;
    int tid = threadIdx.x;

    int jx = tid & 7;
    int ky = tid >> 3;
    sm[ky][jx] = W[(size_t)(FSZ + kt * 32 + ky) * N4H + g * HSZ + blk * 8 + jx];
    __syncthreads();

    int k2 = tid & 31;
    int j2 = tid >> 5;
    g_Wrh[((size_t)blk * MT + g * 8 + j2) * HSZ + kt * 32 + k2] = __float2half_rn(sm[k2][j2]);
}

// ---------------- prep: transpose W[0:F][4H] -> g_Wxth[n][k] fp16 ----------------
__global__ void prep_wxt_kernel(const float* __restrict__ W) {
    __shared__ float sm[32][33];
    int k0 = blockIdx.x * 32;
    int n0 = blockIdx.y * 32;
    int tx = threadIdx.x & 31;
    int ty = threadIdx.x >> 5;
#pragma unroll
    for (int r = 0; r < 4; r++) {
        int row = ty + r * 8;
        sm[row][tx] = W[(size_t)(k0 + row) * N4H + n0 + tx];
    }
    __syncthreads();
#pragma unroll
    for (int r = 0; r < 4; r++) {
        int row = ty + r * 8;
        g_Wxth[(size_t)(n0 + row) * FSZ + k0 + tx] = __float2half_rn(sm[tx][row]);
    }
}

// ---------------- precompute Z = X @ Wx + b (fp16 mma, 128x64 tile, KT=128) ----------------
__global__ __launch_bounds__(256, 2)
void precompute_mma_kernel(const float* __restrict__ bias, float* __restrict__ Z) {
    extern __shared__ char dsm_raw[];
    const uint32_t raw_base = smem_u32(dsm_raw);
    const uint32_t base     = (raw_base + 1023) & ~1023u;

    const int tid  = threadIdx.x;
    const int wid  = tid >> 5;
    const int lane = tid & 31;
    const int wm   = wid >> 1;
    const int wn   = wid & 1;
    const int n0   = blockIdx.x * 64;
    const int m0   = blockIdx.y * 128;

    const int grp = lane >> 3;
    const int r_l = lane & 7;
    const int a_row0 = wm * 32 + ((grp & 1) << 3) + r_l;
    const int a_row1 = a_row0 + 16;
    const int a_cko  = grp >> 1;
    const int b_row0 = wn * 32 + ((grp >> 1) << 3) + r_l;
    const int b_row1 = b_row0 + 16;
    const int b_cko  = grp & 1;

    float c[2][4][4];
#pragma unroll
    for (int mf = 0; mf < 2; mf++)
#pragma unroll
        for (int j = 0; j < 4; j++)
#pragma unroll
            for (int q = 0; q < 4; q++) c[mf][j][q] = 0.0f;

    auto load_tile = [&](int kt, int s) {
        const uint32_t aB = base + s * PC_STAGE_BYTES;
        const uint32_t bB = aB + 32768;
        const int k0 = kt * 128;
#pragma unroll
        for (int i = 0; i < 8; i++) {
            int id = tid + i * 256;
            int row = id >> 4;
            int u   = id & 15;
            CP16(aB + row * 256 + (((uint32_t)u ^ (row & 7)) << 4),
                 g_Xh + (size_t)(m0 + row) * FSZ + k0 + u * 8);
        }
#pragma unroll
        for (int i = 0; i < 4; i++) {
            int id = tid + i * 256;
            int row = id >> 4;
            int u   = id & 15;
            CP16(bB + row * 256 + (((uint32_t)u ^ (row & 7)) << 4),
                 g_Wxth + (size_t)(n0 + row) * FSZ + k0 + u * 8);
        }
    };

    load_tile(0, 0);
    CP_COMMIT();

    for (int kt = 0; kt < FSZ / 128; kt++) {
        if (kt + 1 < FSZ / 128) {
            load_tile(kt + 1, (kt + 1) & 1);
            CP_COMMIT();
            CP_WAIT1();
        } else {
            CP_WAIT0();
        }
        __syncthreads();

        const uint32_t aB = base + (kt & 1) * PC_STAGE_BYTES;
        const uint32_t bB = aB + 32768;
#pragma unroll
        for (int s = 0; s < 8; s++) {
            uint32_t ua = (uint32_t)(s * 2 + a_cko);
            uint32_t a00, a01, a02, a03, a10, a11, a12, a13;
            LDSM_X4(a00, a01, a02, a03,
                    aB + a_row0 * 256 + ((ua ^ (a_row0 & 7)) << 4));
            LDSM_X4(a10, a11, a12, a13,
                    aB + a_row1 * 256 + ((ua ^ (a_row1 & 7)) << 4));

            uint32_t ub = (uint32_t)(s * 2 + b_cko);
            uint32_t b00, b01, b10, b11, b20, b21, b30, b31;
            LDSM_X4(b00, b01, b10, b11,
                    bB + b_row0 * 256 + ((ub ^ (b_row0 & 7)) << 4));
            LDSM_X4(b20, b21, b30, b31,
                    bB + b_row1 * 256 + ((ub ^ (b_row1 & 7)) << 4));

            MMA_F16(c[0][0], a00, a01, a02, a03, b00, b01);
            MMA_F16(c[0][1], a00, a01, a02, a03, b10, b11);
            MMA_F16(c[0][2], a00, a01, a02, a03, b20, b21);
            MMA_F16(c[0][3], a00, a01, a02, a03, b30, b31);
            MMA_F16(c[1][0], a10, a11, a12, a13, b00, b01);
            MMA_F16(c[1][1], a10, a11, a12, a13, b10, b11);
            MMA_F16(c[1][2], a10, a11, a12, a13, b20, b21);
            MMA_F16(c[1][3], a10, a11, a12, a13, b30, b31);
        }
        __syncthreads();
    }

    const int gr = lane >> 2;
    const int qc = lane & 3;
#pragma unroll
    for (int mf = 0; mf < 2; mf++) {
#pragma unroll
        for (int j = 0; j < 4; j++) {
            int n = n0 + wn * 32 + j * 8 + 2 * qc;
            float2 bia = *(const float2*)(bias + n);
            int m1 = m0 + wm * 32 + mf * 16 + gr;
            int m2 = m1 + 8;
            float2 v1 = { c[mf][j][0] + bia.x, c[mf][j][1] + bia.y };
            float2 v2 = { c[mf][j][2] + bia.x, c[mf][j][3] + bia.y };
            *(float2*)(Z + ((size_t)(m1 & 127) * BSZ + (m1 >> 7)) * N4H + n) = v1;
            *(float2*)(Z + ((size_t)(m2 & 127) * BSZ + (m2 >> 7)) * N4H + n) = v2;
        }
    }
}

// ---------------- persistent LSTM kernel (fp16, KT=128 x 2 tiles, 2-stage pipeline) ----------------
// grid=128, block=512. Group g (wid>>2): k in [g*256,(g+1)*256), 2 tiles of KT=128.
// wk = (wid>>1)&1 selects k-half (64) within each tile; wn = wid&1 batch half.
// Warp tile 32(m)x32(n), k total 128 per warp (2 tiles x 64).
__global__ __launch_bounds__(512, 1)
void lstm_persist_kernel(float* __restrict__ d_out) {
    extern __shared__ char dsm_raw[];
    const uint32_t raw_base = smem_u32(dsm_raw);
    const uint32_t base     = (raw_base + 1023) & ~1023u;
    const uint32_t aS       = base;
    float* SfAll = (float*)(dsm_raw + (base - raw_base) + A_SMEM_BYTES); // partials overlay B

    const int tid  = threadIdx.x;
    const int wid  = tid >> 5;
    const int lane = tid & 31;
    const int blk  = blockIdx.x;
    const int g    = wid >> 2;            // k-group 0..3
    const int wk   = (wid >> 1) & 1;      // k-half within tile
    const int wn   = wid & 1;             // batch half
    const int tig  = tid & 127;
    const uint32_t bGroup = base + A_SMEM_BYTES + g * BG_BYTES;

    // ---- load resident A panel (32 rows x 1024 fp16, 2048B/row, swizzled) ----
    {
        const __half* wsrc = g_Wrh + (size_t)blk * MT * HSZ;
#pragma unroll
        for (int i = 0; i < 8; i++) {
            int uix = tid + i * 512;
            int row = uix >> 7;
            int u   = uix & 127;
            CP16(aS + row * 2048 + (((uint32_t)u ^ (row & 7)) << 4),
                 wsrc + (size_t)row * HSZ + u * 8);
        }
        CP_COMMIT();
        CP_WAIT0();
    }
    __syncthreads();

    // lane-dependent ldmatrix address components
    const int grp = lane >> 3;
    const int r_l = lane & 7;
    const int a_row0 = ((grp & 1) << 3) + r_l;
    const int a_row1 = a_row0 + 16;
    const int a_cko  = grp >> 1;
    const int b_row0 = wn * 32 + ((grp >> 1) << 3) + r_l;
    const int b_row1 = b_row0 + 16;
    const int b_cko  = grp & 1;
    const uint32_t aAddr0 = aS + a_row0 * 2048;
    const uint32_t aAddr1 = aS + a_row1 * 2048;
    const int a_sw0 = a_row0 & 7;
    const int a_sw1 = a_row1 & 7;
    const int b_sw0 = b_row0 & 7;
    const int b_sw1 = b_row1 & 7;

    // epilogue indices
    const int e_j = tid & 7;
    const int e_b = tid >> 3;
    const int e_hcol = blk * 8 + e_j;
    const int my_quarter = blk >> 5;

    float cst = 0.0f;                     // cell state (register)

    for (int t = 0; t < TSTEPS; t++) {
        const __half* __restrict__ hi = g_h[t & 1];
        __half* __restrict__ ho = g_h[(t + 1) & 1];

        float c[2][4][4];
#pragma unroll
        for (int mh = 0; mh < 2; mh++)
#pragma unroll
            for (int j = 0; j < 4; j++)
#pragma unroll
                for (int q = 0; q < 4; q++) c[mh][j][q] = 0.0f;

        // Z loads (independent of h(t); issue before the wait)
        const float* zp = g_Z + (size_t)t * BSZ * N4H + (size_t)e_b * N4H + blk * 8 + e_j;
        float z0 = __ldg(zp);
        float z1 = __ldg(zp + HSZ);
        float z2 = __ldg(zp + 2 * HSZ);
        float z3 = __ldg(zp + 3 * HSZ);

        // ---- dataflow wait: single poller per group, then group barrier ----
        if (tig == 0) {
            int v;
            const int* p = &g_cnt[t][g];
            do {
                asm volatile("ld.global.acquire.gpu.b32 %0, [%1];" : "=r"(v) : "l"(p) : "memory");
            } while (v < 32);
        }
        BARG(g + 1);

        // fill tile kt (64 rows x 128 fp16 = 16 KB) into stage kt; 8 CP16/thread
        auto fill = [&](int kt) {
            const uint32_t bB = bGroup + kt * 16384;
            const int k0 = g * 256 + kt * 128;
#pragma unroll
            for (int i = 0; i < 8; i++) {
                int id  = tig + i * 128;      // 0..1023 units
                int row = id >> 4;            // 64 rows x 16 units
                int u   = id & 15;
                uint32_t su = (uint32_t)((u & 8) | ((u & 7) ^ (row & 7)));
                CP16(bB + row * 256 + (su << 4),
                     hi + (size_t)row * HSZ + k0 + u * 8);
            }
        };

        fill(0); CP_COMMIT();
        fill(1); CP_COMMIT();

#pragma unroll
        for (int kt = 0; kt < 2; kt++) {
            if (kt == 0) CP_WAIT1(); else CP_WAIT0();
            BARG(g + 1);

            const uint32_t bB = bGroup + kt * 16384;
#pragma unroll
            for (int s = 0; s < 4; s++) {
                // warp k16: g*256 + kt*128 + wk*64 + s*16 -> A unit /8
                uint32_t ua = (uint32_t)(g * 32 + kt * 16 + wk * 8 + s * 2 + a_cko);
                uint32_t a00, a01, a02, a03, a10, a11, a12, a13;
                LDSM_X4(a00, a01, a02, a03, aAddr0 + ((ua ^ a_sw0) << 4));
                LDSM_X4(a10, a11, a12, a13, aAddr1 + ((ua ^ a_sw1) << 4));

                uint32_t u = (uint32_t)(wk * 8 + s * 2 + b_cko);
                uint32_t su0 = (u & 8) | ((u & 7) ^ b_sw0);
                uint32_t su1 = (u & 8) | ((u & 7) ^ b_sw1);
                uint32_t b00, b01, b10, b11, b20, b21, b30, b31;
                LDSM_X4(b00, b01, b10, b11, bB + b_row0 * 256 + (su0 << 4));
                LDSM_X4(b20, b21, b30, b31, bB + b_row1 * 256 + (su1 << 4));

                MMA_F16(c[0][0], a00, a01, a02, a03, b00, b01);
                MMA_F16(c[0][1], a00, a01, a02, a03, b10, b11);
                MMA_F16(c[0][2], a00, a01, a02, a03, b20, b21);
                MMA_F16(c[0][3], a00, a01, a02, a03, b30, b31);
                MMA_F16(c[1][0], a10, a11, a12, a13, b00, b01);
                MMA_F16(c[1][1], a10, a11, a12, a13, b10, b11);
                MMA_F16(c[1][2], a10, a11, a12, a13, b20, b21);
                MMA_F16(c[1][3], a10, a11, a12, a13, b30, b31);
            }
        }

        // ---- stash partials: region (g, wk), S[m*65+n], wn disjoint n ----
        {
            float* S = SfAll + g * (BG_BYTES / 4) + wk * 2080;   // 2080 = 32*65
            const int gr = lane >> 2;
            const int qc = lane & 3;
            BARG(g + 1);   // group warps done with LDSM before overwriting B region
#pragma unroll
            for (int mh = 0; mh < 2; mh++) {
#pragma unroll
                for (int j = 0; j < 4; j++) {
                    int m = mh * 16 + gr;
                    int n = wn * 32 + j * 8 + 2 * qc;
                    S[m * 65 + n]           = c[mh][j][0];
                    S[m * 65 + n + 1]       = c[mh][j][1];
                    S[(m + 8) * 65 + n]     = c[mh][j][2];
                    S[(m + 8) * 65 + n + 1] = c[mh][j][3];
                }
            }
        }
        __syncthreads();

        // ---- gate epilogue: 512 cells, 1 per thread; sum 8 partial regions + Z ----
        float z[4] = { z0, z1, z2, z3 };
#pragma unroll
        for (int gate = 0; gate < 4; gate++) {
            float s = z[gate];
            int off = (gate * 8 + e_j) * 65 + e_b;
#pragma unroll
            for (int g2 = 0; g2 < 4; g2++) {
                s += SfAll[g2 * (BG_BYTES / 4) + off];
                s += SfAll[g2 * (BG_BYTES / 4) + 2080 + off];
            }
            z[gate] = s;
        }
        float si = 1.0f / (1.0f + __expf(-z[0]));
        float sf = 1.0f / (1.0f + __expf(-(z[2] + 1.0f)));   // forget bias = 1.0
        float so = 1.0f / (1.0f + __expf(-z[3]));
        float tj = tanhf(z[1]);

        cst = cst * sf + si * tj;
        float h_new = tanhf(cst) * so;

        ho[(size_t)e_b * HSZ + e_hcol] = __float2half_rn(h_new);

        // ---- publish h(t+1) slice; d_out store overlaps next step's wait ----
        __threadfence();
        __syncthreads();
        if (tid == 0 && t + 1 < TSTEPS) {
            asm volatile("red.release.gpu.global.add.u32 [%0], %1;"
                         :: "l"(&g_cnt[t + 1][my_quarter]), "r"(1u) : "memory");
        }
        d_out[((size_t)e_b * TSTEPS + t) * HSZ + e_hcol] = h_new;
    }
}

// ---------------- launcher ----------------
extern "C" void kernel_launch(void* const* d_in, const int* in_sizes, int n_in,
                              void* d_out, int out_size) {
    const float* x = (const float*)d_in[0];   // [B, T, F]
    const float* W = (const float*)d_in[1];   // [F+H, 4H]
    const float* b = (const float*)d_in[2];   // [4H]
    float* out = (float*)d_out;               // [B, T, H]

    static bool attr_done = false;
    if (!attr_done) {
        cudaFuncSetAttribute(lstm_persist_kernel, cudaFuncAttributeMaxDynamicSharedMemorySize,
                             DSMEM_BYTES);
        cudaFuncSetAttribute(precompute_mma_kernel, cudaFuncAttributeMaxDynamicSharedMemorySize,
                             PC_DSMEM);
        attr_done = true;
    }

    float* zbuf;
    cudaGetSymbolAddress((void**)&zbuf, g_Z);

    init_state_kernel<<<(BSZ * HSZ + 255) / 256, 256>>>();
    prep_x_kernel<<<(BSZ * TSTEPS * FSZ) / (256 * 4), 256>>>(x);
    prep_w_kernel<<<NCTA * 4 * 32, 256>>>(W);
    {
        dim3 g(FSZ / 32, N4H / 32);
        prep_wxt_kernel<<<g, 256>>>(W);
    }
    {
        dim3 g(N4H / 64, (BSZ * TSTEPS) / 128);   // (64, 64)
        precompute_mma_kernel<<<g, 256, PC_DSMEM>>>(b, zbuf);
    }
    lstm_persist_kernel<<<NCTA, 512, DSMEM_BYTES>>>(out);
}

// round 17
// speedup vs baseline: 1.2222x; 1.1893x over previous
#include <cuda_runtime.h>
#include <cuda_fp16.h>
#include <cstdint>
#include <math.h>

// Problem constants
#define TSTEPS 128
#define BSZ    64
#define FSZ    1024
#define HSZ    1024
#define N4H    4096   // 4*H

// Persistent step-GEMM (fp16): 4 k-groups x (2 k-sub x 2 n-half) warps, warp tile 32x32
// B: 2 tiles of KT=128 (16 KB each), 2-stage pipeline. Partials stride 68 (conflict-free).
#define NCTA   128
#define MT     32
#define A_SMEM_BYTES  65536             // 32 rows x 1024 fp16 (2048B/row, swizzled, resident)
#define BG_BYTES      32768             // per-group B: 2 stages x 16 KB (64 rows x 256B)
#define DSMEM_BYTES   (A_SMEM_BYTES + 4 * BG_BYTES + 1024)   // 197632
#define P_STRIDE      68                // partials row stride (68 mod 32 = 4 -> conflict-free)
#define P_REGION      (32 * P_STRIDE)   // 2176 floats per (g, wk) region

// Precompute GEMM (fp16): CTA tile 128x64, warp 32x32, KT=128, 2 stages
#define PC_STAGE_BYTES 49152            // A 32 KB (128x256B) + B 16 KB (64x256B)
#define PC_DSMEM (2 * PC_STAGE_BYTES + 1024)

// ---------------- device scratch ----------------
__device__ float  g_Z[(size_t)TSTEPS * BSZ * N4H];    // [T][B][4H] x@Wx + b (fp32)
__device__ __half g_Wrh[(size_t)NCTA * MT * HSZ];     // [blk][m][k] fp16 recurrent weights
__device__ __half g_Wxth[(size_t)N4H * FSZ];          // [n][k] fp16 input weights (transposed)
__device__ __half g_Xh[(size_t)BSZ * TSTEPS * FSZ];   // fp16 copy of x
__device__ __half g_h[2][BSZ * HSZ];                  // ping-pong hidden state (fp16)
__device__ int    g_cnt[TSTEPS + 1][4];               // h(t) quarter q ready when ==32

// ---------------- helpers ----------------
__device__ __forceinline__ uint32_t smem_u32(const void* p) {
    uint32_t a;
    asm("{ .reg .u64 t; cvta.to.shared.u64 t, %1; cvt.u32.u64 %0, t; }" : "=r"(a) : "l"(p));
    return a;
}
#define CP16(dst, src) \
    asm volatile("cp.async.cg.shared.global [%0], [%1], 16;" :: "r"(dst), "l"(src) : "memory")
#define CP_COMMIT() asm volatile("cp.async.commit_group;" ::: "memory")
#define CP_WAIT1()  asm volatile("cp.async.wait_group 1;" ::: "memory")
#define CP_WAIT0()  asm volatile("cp.async.wait_group 0;" ::: "memory")
#define BARG(id)    asm volatile("bar.sync %0, 128;" :: "r"(id) : "memory")

#define LDSM_X4(r0, r1, r2, r3, addr) \
    asm volatile("ldmatrix.sync.aligned.m8n8.x4.shared.b16 {%0,%1,%2,%3}, [%4];" \
                 : "=r"(r0), "=r"(r1), "=r"(r2), "=r"(r3) : "r"(addr))

#define MMA_F16(c, a0, a1, a2, a3, b0, b1) \
    asm volatile("mma.sync.aligned.m16n8k16.row.col.f32.f16.f16.f32 " \
                 "{%0,%1,%2,%3}, {%4,%5,%6,%7}, {%8,%9}, {%0,%1,%2,%3};" \
                 : "+f"((c)[0]), "+f"((c)[1]), "+f"((c)[2]), "+f"((c)[3]) \
                 : "r"(a0), "r"(a1), "r"(a2), "r"(a3), "r"(b0), "r"(b1))

// ---------------- init: zero h[0], reset counters ----------------
__global__ void init_state_kernel() {
    int i = blockIdx.x * blockDim.x + threadIdx.x;
    if (i < BSZ * HSZ) { g_h[0][i] = __float2half(0.0f); }
    if (i < (TSTEPS + 1) * 4) { ((int*)g_cnt)[i] = (i < 4) ? 32 : 0; }
}

// ---------------- prep: x -> fp16 ----------------
__global__ void prep_x_kernel(const float* __restrict__ X) {
    int idx = (blockIdx.x * blockDim.x + threadIdx.x) * 4;
    float4 v = *(const float4*)(X + idx);
    __half2 h0 = __floats2half2_rn(v.x, v.y);
    __half2 h1 = __floats2half2_rn(v.z, v.w);
    *(uint2*)&g_Xh[idx] = make_uint2(*(uint32_t*)&h0, *(uint32_t*)&h1);
}

// ---------------- prep: recurrent weights -> [blk][m=g*8+j][k] fp16 ----------------
__global__ void prep_w_kernel(const float* __restrict__ W) {
    __shared__ float sm[32][9];
    int bx  = blockIdx.x;
    int kt  = bx & 31;
    int g   = (bx >> 5) & 3;
    int blk = bx >> 7;
    int tid = threadIdx.x;

    int jx = tid & 7;
    int ky = tid >> 3;
    sm[ky][jx] = W[(size_t)(FSZ + kt * 32 + ky) * N4H + g * HSZ + blk * 8 + jx];
    __syncthreads();

    int k2 = tid & 31;
    int j2 = tid >> 5;
    g_Wrh[((size_t)blk * MT + g * 8 + j2) * HSZ + kt * 32 + k2] = __float2half_rn(sm[k2][j2]);
}

// ---------------- prep: transpose W[0:F][4H] -> g_Wxth[n][k] fp16 ----------------
__global__ void prep_wxt_kernel(const float* __restrict__ W) {
    __shared__ float sm[32][33];
    int k0 = blockIdx.x * 32;
    int n0 = blockIdx.y * 32;
    int tx = threadIdx.x & 31;
    int ty = threadIdx.x >> 5;
#pragma unroll
    for (int r = 0; r < 4; r++) {
        int row = ty + r * 8;
        sm[row][tx] = W[(size_t)(k0 + row) * N4H + n0 + tx];
    }
    __syncthreads();
#pragma unroll
    for (int r = 0; r < 4; r++) {
        int row = ty + r * 8;
        g_Wxth[(size_t)(n0 + row) * FSZ + k0 + tx] = __float2half_rn(sm[tx][row]);
    }
}

// ---------------- precompute Z = X @ Wx + b (fp16 mma, 128x64 tile, KT=128) ----------------
__global__ __launch_bounds__(256, 2)
void precompute_mma_kernel(const float* __restrict__ bias, float* __restrict__ Z) {
    extern __shared__ char dsm_raw[];
    const uint32_t raw_base = smem_u32(dsm_raw);
    const uint32_t base     = (raw_base + 1023) & ~1023u;

    const int tid  = threadIdx.x;
    const int wid  = tid >> 5;
    const int lane = tid & 31;
    const int wm   = wid >> 1;
    const int wn   = wid & 1;
    const int n0   = blockIdx.x * 64;
    const int m0   = blockIdx.y * 128;

    const int grp = lane >> 3;
    const int r_l = lane & 7;
    const int a_row0 = wm * 32 + ((grp & 1) << 3) + r_l;
    const int a_row1 = a_row0 + 16;
    const int a_cko  = grp >> 1;
    const int b_row0 = wn * 32 + ((grp >> 1) << 3) + r_l;
    const int b_row1 = b_row0 + 16;
    const int b_cko  = grp & 1;

    float c[2][4][4];
#pragma unroll
    for (int mf = 0; mf < 2; mf++)
#pragma unroll
        for (int j = 0; j < 4; j++)
#pragma unroll
            for (int q = 0; q < 4; q++) c[mf][j][q] = 0.0f;

    auto load_tile = [&](int kt, int s) {
        const uint32_t aB = base + s * PC_STAGE_BYTES;
        const uint32_t bB = aB + 32768;
        const int k0 = kt * 128;
#pragma unroll
        for (int i = 0; i < 8; i++) {
            int id = tid + i * 256;
            int row = id >> 4;
            int u   = id & 15;
            CP16(aB + row * 256 + (((uint32_t)u ^ (row & 7)) << 4),
                 g_Xh + (size_t)(m0 + row) * FSZ + k0 + u * 8);
        }
#pragma unroll
        for (int i = 0; i < 4; i++) {
            int id = tid + i * 256;
            int row = id >> 4;
            int u   = id & 15;
            CP16(bB + row * 256 + (((uint32_t)u ^ (row & 7)) << 4),
                 g_Wxth + (size_t)(n0 + row) * FSZ + k0 + u * 8);
        }
    };

    load_tile(0, 0);
    CP_COMMIT();

    for (int kt = 0; kt < FSZ / 128; kt++) {
        if (kt + 1 < FSZ / 128) {
            load_tile(kt + 1, (kt + 1) & 1);
            CP_COMMIT();
            CP_WAIT1();
        } else {
            CP_WAIT0();
        }
        __syncthreads();

        const uint32_t aB = base + (kt & 1) * PC_STAGE_BYTES;
        const uint32_t bB = aB + 32768;
#pragma unroll
        for (int s = 0; s < 8; s++) {
            uint32_t ua = (uint32_t)(s * 2 + a_cko);
            uint32_t a00, a01, a02, a03, a10, a11, a12, a13;
            LDSM_X4(a00, a01, a02, a03,
                    aB + a_row0 * 256 + ((ua ^ (a_row0 & 7)) << 4));
            LDSM_X4(a10, a11, a12, a13,
                    aB + a_row1 * 256 + ((ua ^ (a_row1 & 7)) << 4));

            uint32_t ub = (uint32_t)(s * 2 + b_cko);
            uint32_t b00, b01, b10, b11, b20, b21, b30, b31;
            LDSM_X4(b00, b01, b10, b11,
                    bB + b_row0 * 256 + ((ub ^ (b_row0 & 7)) << 4));
            LDSM_X4(b20, b21, b30, b31,
                    bB + b_row1 * 256 + ((ub ^ (b_row1 & 7)) << 4));

            MMA_F16(c[0][0], a00, a01, a02, a03, b00, b01);
            MMA_F16(c[0][1], a00, a01, a02, a03, b10, b11);
            MMA_F16(c[0][2], a00, a01, a02, a03, b20, b21);
            MMA_F16(c[0][3], a00, a01, a02, a03, b30, b31);
            MMA_F16(c[1][0], a10, a11, a12, a13, b00, b01);
            MMA_F16(c[1][1], a10, a11, a12, a13, b10, b11);
            MMA_F16(c[1][2], a10, a11, a12, a13, b20, b21);
            MMA_F16(c[1][3], a10, a11, a12, a13, b30, b31);
        }
        __syncthreads();
    }

    const int gr = lane >> 2;
    const int qc = lane & 3;
#pragma unroll
    for (int mf = 0; mf < 2; mf++) {
#pragma unroll
        for (int j = 0; j < 4; j++) {
            int n = n0 + wn * 32 + j * 8 + 2 * qc;
            float2 bia = *(const float2*)(bias + n);
            int m1 = m0 + wm * 32 + mf * 16 + gr;
            int m2 = m1 + 8;
            float2 v1 = { c[mf][j][0] + bia.x, c[mf][j][1] + bia.y };
            float2 v2 = { c[mf][j][2] + bia.x, c[mf][j][3] + bia.y };
            *(float2*)(Z + ((size_t)(m1 & 127) * BSZ + (m1 >> 7)) * N4H + n) = v1;
            *(float2*)(Z + ((size_t)(m2 & 127) * BSZ + (m2 >> 7)) * N4H + n) = v2;
        }
    }
}

// ---------------- persistent LSTM kernel (fp16, KT=128 x 2 tiles, stride-68 partials) ----------------
__global__ __launch_bounds__(512, 1)
void lstm_persist_kernel(float* __restrict__ d_out) {
    extern __shared__ char dsm_raw[];
    const uint32_t raw_base = smem_u32(dsm_raw);
    const uint32_t base     = (raw_base + 1023) & ~1023u;
    const uint32_t aS       = base;
    float* SfAll = (float*)(dsm_raw + (base - raw_base) + A_SMEM_BYTES); // partials overlay B

    const int tid  = threadIdx.x;
    const int wid  = tid >> 5;
    const int lane = tid & 31;
    const int blk  = blockIdx.x;
    const int g    = wid >> 2;            // k-group 0..3
    const int wk   = (wid >> 1) & 1;      // k-half within tile
    const int wn   = wid & 1;             // batch half
    const int tig  = tid & 127;
    const uint32_t bGroup = base + A_SMEM_BYTES + g * BG_BYTES;

    // ---- load resident A panel (32 rows x 1024 fp16, 2048B/row, swizzled) ----
    {
        const __half* wsrc = g_Wrh + (size_t)blk * MT * HSZ;
#pragma unroll
        for (int i = 0; i < 8; i++) {
            int uix = tid + i * 512;
            int row = uix >> 7;
            int u   = uix & 127;
            CP16(aS + row * 2048 + (((uint32_t)u ^ (row & 7)) << 4),
                 wsrc + (size_t)row * HSZ + u * 8);
        }
        CP_COMMIT();
        CP_WAIT0();
    }
    __syncthreads();

    // lane-dependent ldmatrix address components
    const int grp = lane >> 3;
    const int r_l = lane & 7;
    const int a_row0 = ((grp & 1) << 3) + r_l;
    const int a_row1 = a_row0 + 16;
    const int a_cko  = grp >> 1;
    const int b_row0 = wn * 32 + ((grp >> 1) << 3) + r_l;
    const int b_row1 = b_row0 + 16;
    const int b_cko  = grp & 1;
    const uint32_t aAddr0 = aS + a_row0 * 2048;
    const uint32_t aAddr1 = aS + a_row1 * 2048;
    const int a_sw0 = a_row0 & 7;
    const int a_sw1 = a_row1 & 7;
    const int b_sw0 = b_row0 & 7;
    const int b_sw1 = b_row1 & 7;

    // epilogue indices
    const int e_j = tid & 7;
    const int e_b = tid >> 3;
    const int e_hcol = blk * 8 + e_j;
    const int my_quarter = blk >> 5;

    float cst = 0.0f;                     // cell state (register)

    for (int t = 0; t < TSTEPS; t++) {
        const __half* __restrict__ hi = g_h[t & 1];
        __half* __restrict__ ho = g_h[(t + 1) & 1];

        float c[2][4][4];
#pragma unroll
        for (int mh = 0; mh < 2; mh++)
#pragma unroll
            for (int j = 0; j < 4; j++)
#pragma unroll
                for (int q = 0; q < 4; q++) c[mh][j][q] = 0.0f;

        // Z loads (independent of h(t); issue before the wait)
        const float* zp = g_Z + (size_t)t * BSZ * N4H + (size_t)e_b * N4H + blk * 8 + e_j;
        float z0 = __ldg(zp);
        float z1 = __ldg(zp + HSZ);
        float z2 = __ldg(zp + 2 * HSZ);
        float z3 = __ldg(zp + 3 * HSZ);

        // ---- dataflow wait: single poller per group, then group barrier ----
        if (tig == 0) {
            int v;
            const int* p = &g_cnt[t][g];
            do {
                asm volatile("ld.global.acquire.gpu.b32 %0, [%1];" : "=r"(v) : "l"(p) : "memory");
            } while (v < 32);
        }
        BARG(g + 1);

        // fill tile kt (64 rows x 128 fp16 = 16 KB) into stage kt; 8 CP16/thread
        auto fill = [&](int kt) {
            const uint32_t bB = bGroup + kt * 16384;
            const int k0 = g * 256 + kt * 128;
#pragma unroll
            for (int i = 0; i < 8; i++) {
                int id  = tig + i * 128;      // 0..1023 units
                int row = id >> 4;            // 64 rows x 16 units
                int u   = id & 15;
                uint32_t su = (uint32_t)((u & 8) | ((u & 7) ^ (row & 7)));
                CP16(bB + row * 256 + (su << 4),
                     hi + (size_t)row * HSZ + k0 + u * 8);
            }
        };

        fill(0); CP_COMMIT();
        fill(1); CP_COMMIT();

#pragma unroll
        for (int kt = 0; kt < 2; kt++) {
            if (kt == 0) CP_WAIT1(); else CP_WAIT0();
            BARG(g + 1);

            const uint32_t bB = bGroup + kt * 16384;
#pragma unroll
            for (int s = 0; s < 4; s++) {
                uint32_t ua = (uint32_t)(g * 32 + kt * 16 + wk * 8 + s * 2 + a_cko);
                uint32_t a00, a01, a02, a03, a10, a11, a12, a13;
                LDSM_X4(a00, a01, a02, a03, aAddr0 + ((ua ^ a_sw0) << 4));
                LDSM_X4(a10, a11, a12, a13, aAddr1 + ((ua ^ a_sw1) << 4));

                uint32_t u = (uint32_t)(wk * 8 + s * 2 + b_cko);
                uint32_t su0 = (u & 8) | ((u & 7) ^ b_sw0);
                uint32_t su1 = (u & 8) | ((u & 7) ^ b_sw1);
                uint32_t b00, b01, b10, b11, b20, b21, b30, b31;
                LDSM_X4(b00, b01, b10, b11, bB + b_row0 * 256 + (su0 << 4));
                LDSM_X4(b20, b21, b30, b31, bB + b_row1 * 256 + (su1 << 4));

                MMA_F16(c[0][0], a00, a01, a02, a03, b00, b01);
                MMA_F16(c[0][1], a00, a01, a02, a03, b10, b11);
                MMA_F16(c[0][2], a00, a01, a02, a03, b20, b21);
                MMA_F16(c[0][3], a00, a01, a02, a03, b30, b31);
                MMA_F16(c[1][0], a10, a11, a12, a13, b00, b01);
                MMA_F16(c[1][1], a10, a11, a12, a13, b10, b11);
                MMA_F16(c[1][2], a10, a11, a12, a13, b20, b21);
                MMA_F16(c[1][3], a10, a11, a12, a13, b30, b31);
            }
        }

        // ---- stash partials: region (g, wk), S[m*68+n] float2, wn disjoint n ----
        {
            float* S = SfAll + g * (BG_BYTES / 4) + wk * P_REGION;
            const int gr = lane >> 2;
            const int qc = lane & 3;
            BARG(g + 1);   // group warps done with LDSM before overwriting B region
#pragma unroll
            for (int mh = 0; mh < 2; mh++) {
#pragma unroll
                for (int j = 0; j < 4; j++) {
                    int m = mh * 16 + gr;
                    int n = wn * 32 + j * 8 + 2 * qc;
                    *(float2*)&S[m * P_STRIDE + n]       = make_float2(c[mh][j][0], c[mh][j][1]);
                    *(float2*)&S[(m + 8) * P_STRIDE + n] = make_float2(c[mh][j][2], c[mh][j][3]);
                }
            }
        }
        __syncthreads();

        // ---- gate epilogue: 512 cells, 1 per thread; conflict-free stride-68 reads ----
        float z[4] = { z0, z1, z2, z3 };
#pragma unroll
        for (int gate = 0; gate < 4; gate++) {
            float s = z[gate];
            int off = (gate * 8 + e_j) * P_STRIDE + e_b;
#pragma unroll
            for (int g2 = 0; g2 < 4; g2++) {
                s += SfAll[g2 * (BG_BYTES / 4) + off];
                s += SfAll[g2 * (BG_BYTES / 4) + P_REGION + off];
            }
            z[gate] = s;
        }
        float si = 1.0f / (1.0f + __expf(-z[0]));
        float sf = 1.0f / (1.0f + __expf(-(z[2] + 1.0f)));   // forget bias = 1.0
        float so = 1.0f / (1.0f + __expf(-z[3]));
        float tj = tanhf(z[1]);

        cst = cst * sf + si * tj;
        float h_new = tanhf(cst) * so;

        ho[(size_t)e_b * HSZ + e_hcol] = __float2half_rn(h_new);

        // ---- publish h(t+1) slice; d_out store overlaps next step's wait ----
        __threadfence();
        __syncthreads();
        if (tid == 0 && t + 1 < TSTEPS) {
            asm volatile("red.release.gpu.global.add.u32 [%0], %1;"
                         :: "l"(&g_cnt[t + 1][my_quarter]), "r"(1u) : "memory");
        }
        d_out[((size_t)e_b * TSTEPS + t) * HSZ + e_hcol] = h_new;
    }
}

// ---------------- launcher ----------------
extern "C" void kernel_launch(void* const* d_in, const int* in_sizes, int n_in,
                              void* d_out, int out_size) {
    const float* x = (const float*)d_in[0];   // [B, T, F]
    const float* W = (const float*)d_in[1];   // [F+H, 4H]
    const float* b = (const float*)d_in[2];   // [4H]
    float* out = (float*)d_out;               // [B, T, H]

    static bool attr_done = false;
    if (!attr_done) {
        cudaFuncSetAttribute(lstm_persist_kernel, cudaFuncAttributeMaxDynamicSharedMemorySize,
                             DSMEM_BYTES);
        cudaFuncSetAttribute(precompute_mma_kernel, cudaFuncAttributeMaxDynamicSharedMemorySize,
                             PC_DSMEM);
        attr_done = true;
    }

    float* zbuf;
    cudaGetSymbolAddress((void**)&zbuf, g_Z);

    init_state_kernel<<<(BSZ * HSZ + 255) / 256, 256>>>();
    prep_x_kernel<<<(BSZ * TSTEPS * FSZ) / (256 * 4), 256>>>(x);
    prep_w_kernel<<<NCTA * 4 * 32, 256>>>(W);
    {
        dim3 g(FSZ / 32, N4H / 32);
        prep_wxt_kernel<<<g, 256>>>(W);
    }
    {
        dim3 g(N4H / 64, (BSZ * TSTEPS) / 128);   // (64, 64)
        precompute_mma_kernel<<<g, 256, PC_DSMEM>>>(b, zbuf);
    }
    lstm_persist_kernel<<<NCTA, 512, DSMEM_BYTES>>>(out);
}